// round 3
// baseline (speedup 1.0000x reference)
#include <cuda_runtime.h>
#include <math.h>

// Problem constants
#define PB 2
#define PL 2048
#define PE 2048
#define PH 16
#define PHD 128

// Scratch (device globals: no allocation allowed in kernel_launch)
__device__ float g_qkv[PB * PL * 3 * PE];        // [B, L, 3E]
__device__ float g_q[PB * PH * PL * PHD];        // [B, H, L, HD]
__device__ float g_k[PB * PH * PL * PHD];
__device__ float g_v[PB * PH * PL * PHD];
__device__ float g_y[PB * PL * PE];              // [B, L, E] (attention output)

// ---------------------------------------------------------------------------
// GEMM (NT): C[M,N] = A[M,K] * B[N,K]^T, all row-major fp32.
// 128x128 tile, BK=16, 256 threads, 8x8 per thread, double-buffered smem.
// M, N, K assumed multiples of 128/128/16 (true for this problem).
// ---------------------------------------------------------------------------
#define BM 128
#define BN 128
#define BK 16
#define SAPAD (BM + 4)

__global__ __launch_bounds__(256, 2) void gemm_nt(
    const float* __restrict__ A, const float* __restrict__ B,
    float* __restrict__ C, int M, int N, int K)
{
    __shared__ __align__(16) float sA[2][BK][SAPAD];
    __shared__ __align__(16) float sB[2][BK][SAPAD];

    const int tid = threadIdx.x;
    const int bm = blockIdx.y * BM;
    const int bn = blockIdx.x * BN;
    const int ty = tid >> 4;       // 0..15 : row group (8 rows)
    const int tx = tid & 15;       // 0..15 : col group (4 + 4 cols)
    const int lr = tid >> 1;       // 0..127 load row
    const int lc = (tid & 1) * 8;  // 0 or 8 load col base (k)

    const float* Ag = A + (size_t)(bm + lr) * K + lc;
    const float* Bg = B + (size_t)(bn + lr) * K + lc;

    float acc[8][8];
#pragma unroll
    for (int i = 0; i < 8; ++i)
#pragma unroll
        for (int j = 0; j < 8; ++j) acc[i][j] = 0.f;

    float4 a0, a1, b0, b1;
    a0 = *(const float4*)(Ag);
    a1 = *(const float4*)(Ag + 4);
    b0 = *(const float4*)(Bg);
    b1 = *(const float4*)(Bg + 4);

    // store tile 0 to buffer 0
    {
        sA[0][lc + 0][lr] = a0.x; sA[0][lc + 1][lr] = a0.y;
        sA[0][lc + 2][lr] = a0.z; sA[0][lc + 3][lr] = a0.w;
        sA[0][lc + 4][lr] = a1.x; sA[0][lc + 5][lr] = a1.y;
        sA[0][lc + 6][lr] = a1.z; sA[0][lc + 7][lr] = a1.w;
        sB[0][lc + 0][lr] = b0.x; sB[0][lc + 1][lr] = b0.y;
        sB[0][lc + 2][lr] = b0.z; sB[0][lc + 3][lr] = b0.w;
        sB[0][lc + 4][lr] = b1.x; sB[0][lc + 5][lr] = b1.y;
        sB[0][lc + 6][lr] = b1.z; sB[0][lc + 7][lr] = b1.w;
    }
    __syncthreads();

    const int nt = K / BK;
    int buf = 0;
    for (int t = 0; t < nt; ++t) {
        if (t + 1 < nt) {
            const float* Ag2 = Ag + (t + 1) * BK;
            const float* Bg2 = Bg + (t + 1) * BK;
            a0 = *(const float4*)(Ag2);
            a1 = *(const float4*)(Ag2 + 4);
            b0 = *(const float4*)(Bg2);
            b1 = *(const float4*)(Bg2 + 4);
        }
#pragma unroll
        for (int k = 0; k < BK; ++k) {
            float ra[8], rb[8];
            *(float4*)(ra)     = *(const float4*)&sA[buf][k][ty * 8];
            *(float4*)(ra + 4) = *(const float4*)&sA[buf][k][ty * 8 + 4];
            *(float4*)(rb)     = *(const float4*)&sB[buf][k][tx * 4];
            *(float4*)(rb + 4) = *(const float4*)&sB[buf][k][64 + tx * 4];
#pragma unroll
            for (int i = 0; i < 8; ++i)
#pragma unroll
                for (int j = 0; j < 8; ++j)
                    acc[i][j] += ra[i] * rb[j];
        }
        if (t + 1 < nt) {
            int nb = buf ^ 1;
            sA[nb][lc + 0][lr] = a0.x; sA[nb][lc + 1][lr] = a0.y;
            sA[nb][lc + 2][lr] = a0.z; sA[nb][lc + 3][lr] = a0.w;
            sA[nb][lc + 4][lr] = a1.x; sA[nb][lc + 5][lr] = a1.y;
            sA[nb][lc + 6][lr] = a1.z; sA[nb][lc + 7][lr] = a1.w;
            sB[nb][lc + 0][lr] = b0.x; sB[nb][lc + 1][lr] = b0.y;
            sB[nb][lc + 2][lr] = b0.z; sB[nb][lc + 3][lr] = b0.w;
            sB[nb][lc + 4][lr] = b1.x; sB[nb][lc + 5][lr] = b1.y;
            sB[nb][lc + 6][lr] = b1.z; sB[nb][lc + 7][lr] = b1.w;
        }
        __syncthreads();
        buf ^= 1;
    }

#pragma unroll
    for (int i = 0; i < 8; ++i) {
        size_t r = (size_t)(bm + ty * 8 + i) * N;
        float4 c0 = make_float4(acc[i][0], acc[i][1], acc[i][2], acc[i][3]);
        float4 c1 = make_float4(acc[i][4], acc[i][5], acc[i][6], acc[i][7]);
        *(float4*)&C[r + bn + tx * 4]      = c0;
        *(float4*)&C[r + bn + 64 + tx * 4] = c1;
    }
}

// ---------------------------------------------------------------------------
// RoPE + QKV split/permute: g_qkv [B,L,3E] -> q,k (roped), v in [B,H,L,HD]
// one thread per (b,l,h,pair)
// ---------------------------------------------------------------------------
__global__ __launch_bounds__(256) void rope_split_kernel(
    const float* __restrict__ qkv, const float* __restrict__ rope,
    float* __restrict__ q, float* __restrict__ k, float* __restrict__ v)
{
    int idx = blockIdx.x * blockDim.x + threadIdx.x;   // b,l,h,i flattened
    int i = idx & 63;
    int h = (idx >> 6) & (PH - 1);
    int l = (idx >> 10) & (PL - 1);
    int b = idx >> 21;

    float sn = rope[(l * 64 + i) * 2 + 0];
    float cs = rope[(l * 64 + i) * 2 + 1];

    size_t base = ((size_t)(b * PL + l)) * (3 * PE) + h * PHD + 2 * i;
    float q0 = qkv[base];
    float q1 = qkv[base + 1];
    float k0 = qkv[base + PE];
    float k1 = qkv[base + PE + 1];
    float v0 = qkv[base + 2 * PE];
    float v1 = qkv[base + 2 * PE + 1];

    size_t o = ((size_t)((b * PH + h) * PL + l)) * PHD + 2 * i;
    q[o]     = q0 * cs - q1 * sn;
    q[o + 1] = q1 * cs + q0 * sn;
    k[o]     = k0 * cs - k1 * sn;
    k[o + 1] = k1 * cs + k0 * sn;
    v[o]     = v0;
    v[o + 1] = v1;
}

// ---------------------------------------------------------------------------
// Flash attention (causal), fp32. 64 q-rows x 64 k-rows per tile, HD=128.
// Block: 256 threads (16x16). Thread (ty,tx): S rows ty*4..+3, S cols tx*4..+3,
// O rows ty*4..+3, O cols {tx*4..+3, 64+tx*4..+3}.
// smem: QT[128][68], KT[128][68] (d-major, padded), V[64][132], P[64][64].
// ---------------------------------------------------------------------------
#define SQT_ST 68
#define SV_ST 132
#define ATT_SM_FLOATS (128 * SQT_ST + 128 * SQT_ST + 64 * SV_ST + 64 * 64)
#define ATT_SM_BYTES (ATT_SM_FLOATS * 4)

__global__ __launch_bounds__(256, 1) void attn_kernel(
    const float* __restrict__ Q, const float* __restrict__ K,
    const float* __restrict__ V, float* __restrict__ Y)
{
    extern __shared__ __align__(16) float sm[];
    float* sQT = sm;                         // 128 x 68 (d-major)
    float* sKT = sQT + 128 * SQT_ST;         // 128 x 68 (d-major)
    float* sV  = sKT + 128 * SQT_ST;         // 64 x 132 (row-major)
    float* sP  = sV + 64 * SV_ST;            // 64 x 64

    const int qt = blockIdx.x;
    const int h  = blockIdx.y;
    const int b  = blockIdx.z;
    const int tid = threadIdx.x;
    const int ty = tid >> 4;
    const int tx = tid & 15;
    const int qbase = qt * 64;
    const size_t hb = ((size_t)(b * PH + h)) * PL * PHD;

    const int lrow = tid & 63;           // tile row for loads
    const int ldb  = (tid >> 6) * 32;    // d-offset for loads

    // load Q tile transposed
    {
        const float* qs = Q + hb + (size_t)(qbase + lrow) * PHD + ldb;
#pragma unroll
        for (int u = 0; u < 32; u += 4) {
            float4 f = *(const float4*)(qs + u);
            sQT[(ldb + u + 0) * SQT_ST + lrow] = f.x;
            sQT[(ldb + u + 1) * SQT_ST + lrow] = f.y;
            sQT[(ldb + u + 2) * SQT_ST + lrow] = f.z;
            sQT[(ldb + u + 3) * SQT_ST + lrow] = f.w;
        }
    }

    float m_i[4], l_i[4], o[4][8];
#pragma unroll
    for (int i = 0; i < 4; ++i) {
        m_i[i] = -1e30f;
        l_i[i] = 0.f;
#pragma unroll
        for (int j = 0; j < 8; ++j) o[i][j] = 0.f;
    }
    __syncthreads();

    const float scale = 0.08838834764831845f;  // 1/sqrt(128)

    for (int kt = 0; kt <= qt; ++kt) {
        const int kbase = kt * 64;
        // load K (transposed) and V tiles
        {
            const float* ks = K + hb + (size_t)(kbase + lrow) * PHD + ldb;
#pragma unroll
            for (int u = 0; u < 32; u += 4) {
                float4 f = *(const float4*)(ks + u);
                sKT[(ldb + u + 0) * SQT_ST + lrow] = f.x;
                sKT[(ldb + u + 1) * SQT_ST + lrow] = f.y;
                sKT[(ldb + u + 2) * SQT_ST + lrow] = f.z;
                sKT[(ldb + u + 3) * SQT_ST + lrow] = f.w;
            }
            const float* vs = V + hb + (size_t)(kbase + lrow) * PHD + ldb;
            float* vd = sV + lrow * SV_ST + ldb;
#pragma unroll
            for (int u = 0; u < 32; u += 4)
                *(float4*)(vd + u) = *(const float4*)(vs + u);
        }
        __syncthreads();

        // S = Q K^T for this tile pair
        float s[4][4];
#pragma unroll
        for (int i = 0; i < 4; ++i)
#pragma unroll
            for (int j = 0; j < 4; ++j) s[i][j] = 0.f;

#pragma unroll 4
        for (int d = 0; d < 128; ++d) {
            float4 qv = *(const float4*)(sQT + d * SQT_ST + ty * 4);
            float4 kv = *(const float4*)(sKT + d * SQT_ST + tx * 4);
            float qa[4] = {qv.x, qv.y, qv.z, qv.w};
            float ka[4] = {kv.x, kv.y, kv.z, kv.w};
#pragma unroll
            for (int i = 0; i < 4; ++i)
#pragma unroll
                for (int j = 0; j < 4; ++j)
                    s[i][j] += qa[i] * ka[j];
        }

        // scale + causal mask (only on the diagonal tile)
        if (kt == qt) {
#pragma unroll
            for (int i = 0; i < 4; ++i)
#pragma unroll
                for (int j = 0; j < 4; ++j)
                    s[i][j] = (tx * 4 + j > ty * 4 + i) ? -1e30f : s[i][j] * scale;
        } else {
#pragma unroll
            for (int i = 0; i < 4; ++i)
#pragma unroll
                for (int j = 0; j < 4; ++j)
                    s[i][j] *= scale;
        }

        // online softmax update (rows replicated across the 16 tx lanes)
        float alpha[4];
#pragma unroll
        for (int i = 0; i < 4; ++i) {
            float rm = fmaxf(fmaxf(s[i][0], s[i][1]), fmaxf(s[i][2], s[i][3]));
#pragma unroll
            for (int off = 8; off > 0; off >>= 1)
                rm = fmaxf(rm, __shfl_xor_sync(0xffffffffu, rm, off));
            float mnew = fmaxf(m_i[i], rm);
            alpha[i] = __expf(m_i[i] - mnew);
            float rs = 0.f;
#pragma unroll
            for (int j = 0; j < 4; ++j) {
                s[i][j] = __expf(s[i][j] - mnew);
                rs += s[i][j];
            }
#pragma unroll
            for (int off = 8; off > 0; off >>= 1)
                rs += __shfl_xor_sync(0xffffffffu, rs, off);
            l_i[i] = l_i[i] * alpha[i] + rs;
            m_i[i] = mnew;
        }

        // rescale O, stage P
#pragma unroll
        for (int i = 0; i < 4; ++i) {
#pragma unroll
            for (int j = 0; j < 8; ++j) o[i][j] *= alpha[i];
            float4 p4 = make_float4(s[i][0], s[i][1], s[i][2], s[i][3]);
            *(float4*)&sP[(ty * 4 + i) * 64 + tx * 4] = p4;
        }
        __syncthreads();

        // O += P V
#pragma unroll 4
        for (int kk = 0; kk < 64; ++kk) {
            float4 va = *(const float4*)(sV + kk * SV_ST + tx * 4);
            float4 vb = *(const float4*)(sV + kk * SV_ST + 64 + tx * 4);
#pragma unroll
            for (int i = 0; i < 4; ++i) {
                float p = sP[(ty * 4 + i) * 64 + kk];
                o[i][0] += p * va.x; o[i][1] += p * va.y;
                o[i][2] += p * va.z; o[i][3] += p * va.w;
                o[i][4] += p * vb.x; o[i][5] += p * vb.y;
                o[i][6] += p * vb.z; o[i][7] += p * vb.w;
            }
        }
        __syncthreads();
    }

    // epilogue: normalize + write Y[b, l, h*128 + c]
#pragma unroll
    for (int i = 0; i < 4; ++i) {
        float inv = 1.f / l_i[i];
        size_t r = ((size_t)(b * PL + qbase + ty * 4 + i)) * PE + h * PHD;
        float4 y0 = make_float4(o[i][0] * inv, o[i][1] * inv, o[i][2] * inv, o[i][3] * inv);
        float4 y1 = make_float4(o[i][4] * inv, o[i][5] * inv, o[i][6] * inv, o[i][7] * inv);
        *(float4*)&Y[r + tx * 4]      = y0;
        *(float4*)&Y[r + 64 + tx * 4] = y1;
    }
}

// ---------------------------------------------------------------------------
// launch
// ---------------------------------------------------------------------------
extern "C" void kernel_launch(void* const* d_in, const int* in_sizes, int n_in,
                              void* d_out, int out_size)
{
    (void)in_sizes; (void)n_in; (void)out_size;
    const float* x      = (const float*)d_in[0];
    const float* rope   = (const float*)d_in[1];
    const float* w_attn = (const float*)d_in[2];
    const float* w_proj = (const float*)d_in[3];
    float* out = (float*)d_out;

    float *qkv, *q, *k, *v, *y;
    cudaGetSymbolAddress((void**)&qkv, g_qkv);
    cudaGetSymbolAddress((void**)&q, g_q);
    cudaGetSymbolAddress((void**)&k, g_k);
    cudaGetSymbolAddress((void**)&v, g_v);
    cudaGetSymbolAddress((void**)&y, g_y);

    // 1) QKV projection: [4096,2048] x [6144,2048]^T -> [4096,6144]
    gemm_nt<<<dim3(3 * PE / BN, PB * PL / BM), 256>>>(x, w_attn, qkv, PB * PL, 3 * PE, PE);

    // 2) RoPE + split/permute
    rope_split_kernel<<<(PB * PL * PH * 64) / 256, 256>>>(qkv, rope, q, k, v);

    // 3) causal flash attention
    cudaFuncSetAttribute(attn_kernel, cudaFuncAttributeMaxDynamicSharedMemorySize, ATT_SM_BYTES);
    attn_kernel<<<dim3(PL / 64, PH, PB), 256, ATT_SM_BYTES>>>(q, k, v, y);

    // 4) output projection: [4096,2048] x [2048,2048]^T -> [4096,2048]
    gemm_nt<<<dim3(PE / BN, PB * PL / BM), 256>>>(y, w_proj, out, PB * PL, PE, PE);
}

// round 5
// speedup vs baseline: 1.8673x; 1.8673x over previous
#include <cuda_runtime.h>
#include <math.h>
#include <cstdint>

// Problem constants
#define PB 2
#define PL 2048
#define PE 2048
#define PH 16
#define PHD 128

// Scratch (device globals: no allocation allowed in kernel_launch)
__device__ float g_qkv[PB * PL * 3 * PE];        // [B, L, 3E]
__device__ float g_q[PB * PH * PL * PHD];        // [B, H, L, HD]
__device__ float g_k[PB * PH * PL * PHD];
__device__ float g_v[PB * PH * PL * PHD];
__device__ float g_y[PB * PL * PE];              // [B, L, E] (attention output, tf32-rounded)
__device__ float g_xr[PB * PL * PE];             // tf32-rounded x
__device__ float g_war[3 * PE * PE];             // tf32-rounded w_attn
__device__ float g_wpr[PE * PE];                 // tf32-rounded w_proj

// ---------------------------------------------------------------------------
// Helpers
// ---------------------------------------------------------------------------
__device__ __forceinline__ uint32_t smem_u32(const void* p) {
    uint32_t a;
    asm("{ .reg .u64 t; cvta.to.shared.u64 t, %1; cvt.u32.u64 %0, t; }" : "=r"(a) : "l"(p));
    return a;
}

__device__ __forceinline__ float to_tf32(float x) {
    uint32_t u;
    asm("cvt.rna.tf32.f32 %0, %1;" : "=r"(u) : "f"(x));
    return __uint_as_float(u);
}

// ---------------------------------------------------------------------------
// tf32 rounding pass (inputs pre-rounded so HW tf32 truncation is a no-op)
// ---------------------------------------------------------------------------
__global__ __launch_bounds__(256) void round_tf32_kernel(
    const float4* __restrict__ in, float4* __restrict__ out, int n4)
{
    int i = blockIdx.x * blockDim.x + threadIdx.x;
    if (i < n4) {
        float4 v = in[i];
        v.x = to_tf32(v.x); v.y = to_tf32(v.y);
        v.z = to_tf32(v.z); v.w = to_tf32(v.w);
        out[i] = v;
    }
}

// ---------------------------------------------------------------------------
// tf32 HMMA GEMM (NT): C[M,N] = A[M,K] * B[N,K]^T, row-major fp32 (tf32 vals).
// 128x128 CTA tile, BK=32, 256 threads. 8 warps in 2x4 grid, 64x32 per warp,
// mma.sync m16n8k8 tf32. cp.async double buffer. smem stride 36 floats:
// fragment gathers (g*36 + t) mod 32 = g*4+t cover all banks -> conflict-free.
// ---------------------------------------------------------------------------
#define BM 128
#define BN 128
#define BK 32
#define BKP 36
#define TILE_FLOATS (128 * BKP)                      // per matrix per buffer
#define GEMM_SMEM (4 * TILE_FLOATS * 4)              // A0,A1,B0,B1 = 73728 B

__device__ __forceinline__ void cp_async16(uint32_t dst, const void* src) {
    asm volatile("cp.async.cg.shared.global [%0], [%1], 16;" :: "r"(dst), "l"(src));
}
__device__ __forceinline__ void cp_commit() {
    asm volatile("cp.async.commit_group;" ::: "memory");
}
template <int N>
__device__ __forceinline__ void cp_wait() {
    asm volatile("cp.async.wait_group %0;" :: "n"(N) : "memory");
}

__global__ __launch_bounds__(256, 2) void gemm_mma(
    const float* __restrict__ A, const float* __restrict__ B, float* __restrict__ C,
    int M, int N, int K)
{
    extern __shared__ __align__(16) float smg[];
    float* sA = smg;                       // [2][128][36]
    float* sB = smg + 2 * TILE_FLOATS;     // [2][128][36]
    const uint32_t sAu = smem_u32(sA);
    const uint32_t sBu = smem_u32(sB);

    const int tid = threadIdx.x;
    const int wid = tid >> 5;
    const int lane = tid & 31;
    const int bm = blockIdx.y * BM;
    const int bn = blockIdx.x * BN;
    const int wm = wid >> 2;        // 0..1 -> m offset wm*64
    const int wn = wid & 3;         // 0..3 -> n offset wn*32
    const int g = lane >> 2;        // group 0..7
    const int tg = lane & 3;        // thread-in-group 0..3
    const int nt = K >> 5;

    // loader mapping: 1024 float4 chunks per matrix per stage, 4 per thread
    const float* agp[4];
    const float* bgp[4];
    uint32_t asp[4], bsp[4];
#pragma unroll
    for (int j = 0; j < 4; ++j) {
        int c = tid + 256 * j;
        int row = c >> 3, k4 = c & 7;
        agp[j] = A + (size_t)(bm + row) * K + k4 * 4;
        bgp[j] = B + (size_t)(bn + row) * K + k4 * 4;
        asp[j] = (uint32_t)(row * BKP + k4 * 4) * 4;
        bsp[j] = (uint32_t)(row * BKP + k4 * 4) * 4;
    }

    float acc[4][4][4];
#pragma unroll
    for (int i = 0; i < 4; ++i)
#pragma unroll
        for (int j = 0; j < 4; ++j)
#pragma unroll
            for (int q = 0; q < 4; ++q) acc[i][j][q] = 0.f;

    // prefetch stage 0
#pragma unroll
    for (int j = 0; j < 4; ++j) {
        cp_async16(sAu + asp[j], agp[j]);
        cp_async16(sBu + bsp[j], bgp[j]);
    }
    cp_commit();

    const float* aw0 = sA + (wm * 64 + g) * BKP + tg;   // A fragment base (buf 0)
    const float* bw0 = sB + (wn * 32 + g) * BKP + tg;   // B fragment base (buf 0)

    for (int t = 0; t < nt; ++t) {
        if (t + 1 < nt) {
            const int nb = (t + 1) & 1;
            const uint32_t so = nb * TILE_FLOATS * 4;
            const size_t go = (size_t)(t + 1) * BK;
#pragma unroll
            for (int j = 0; j < 4; ++j) {
                cp_async16(sAu + so + asp[j], agp[j] + go);
                cp_async16(sBu + so + bsp[j], bgp[j] + go);
            }
            cp_commit();
            cp_wait<1>();
        } else {
            cp_wait<0>();
        }
        __syncthreads();

        const float* At = aw0 + (t & 1) * TILE_FLOATS;
        const float* Bt = bw0 + (t & 1) * TILE_FLOATS;

#pragma unroll
        for (int ks = 0; ks < 4; ++ks) {
            const int k0 = ks * 8;
            uint32_t af[4][4], bf[4][2];
#pragma unroll
            for (int mt = 0; mt < 4; ++mt) {
                const float* ap = At + mt * 16 * BKP + k0;
                af[mt][0] = __float_as_uint(ap[0]);
                af[mt][1] = __float_as_uint(ap[8 * BKP]);
                af[mt][2] = __float_as_uint(ap[4]);
                af[mt][3] = __float_as_uint(ap[8 * BKP + 4]);
            }
#pragma unroll
            for (int nti = 0; nti < 4; ++nti) {
                const float* bp = Bt + nti * 8 * BKP + k0;
                bf[nti][0] = __float_as_uint(bp[0]);
                bf[nti][1] = __float_as_uint(bp[4]);
            }
#pragma unroll
            for (int mt = 0; mt < 4; ++mt)
#pragma unroll
                for (int nti = 0; nti < 4; ++nti) {
                    asm volatile(
                        "mma.sync.aligned.m16n8k8.row.col.f32.tf32.tf32.f32 "
                        "{%0,%1,%2,%3}, {%4,%5,%6,%7}, {%8,%9}, {%0,%1,%2,%3};"
                        : "+f"(acc[mt][nti][0]), "+f"(acc[mt][nti][1]),
                          "+f"(acc[mt][nti][2]), "+f"(acc[mt][nti][3])
                        : "r"(af[mt][0]), "r"(af[mt][1]), "r"(af[mt][2]), "r"(af[mt][3]),
                          "r"(bf[nti][0]), "r"(bf[nti][1]));
                }
        }
        __syncthreads();
    }

    // epilogue
#pragma unroll
    for (int mt = 0; mt < 4; ++mt) {
        const int row0 = bm + wm * 64 + mt * 16 + g;
#pragma unroll
        for (int nti = 0; nti < 4; ++nti) {
            const int col = bn + wn * 32 + nti * 8 + 2 * tg;
            *(float2*)&C[(size_t)row0 * N + col] =
                make_float2(acc[mt][nti][0], acc[mt][nti][1]);
            *(float2*)&C[(size_t)(row0 + 8) * N + col] =
                make_float2(acc[mt][nti][2], acc[mt][nti][3]);
        }
    }
}

// ---------------------------------------------------------------------------
// RoPE + QKV split/permute: g_qkv [B,L,3E] -> q,k (roped), v in [B,H,L,HD]
// ---------------------------------------------------------------------------
__global__ __launch_bounds__(256) void rope_split_kernel(
    const float* __restrict__ qkv, const float* __restrict__ rope,
    float* __restrict__ q, float* __restrict__ k, float* __restrict__ v)
{
    int idx = blockIdx.x * blockDim.x + threadIdx.x;   // b,l,h,i flattened
    int i = idx & 63;
    int h = (idx >> 6) & (PH - 1);
    int l = (idx >> 10) & (PL - 1);
    int b = idx >> 21;

    float sn = rope[(l * 64 + i) * 2 + 0];
    float cs = rope[(l * 64 + i) * 2 + 1];

    size_t base = ((size_t)(b * PL + l)) * (3 * PE) + h * PHD + 2 * i;
    float q0 = qkv[base];
    float q1 = qkv[base + 1];
    float k0 = qkv[base + PE];
    float k1 = qkv[base + PE + 1];
    float v0 = qkv[base + 2 * PE];
    float v1 = qkv[base + 2 * PE + 1];

    size_t o = ((size_t)((b * PH + h) * PL + l)) * PHD + 2 * i;
    q[o]     = q0 * cs - q1 * sn;
    q[o + 1] = q1 * cs + q0 * sn;
    k[o]     = k0 * cs - k1 * sn;
    k[o + 1] = k1 * cs + k0 * sn;
    v[o]     = v0;
    v[o + 1] = v1;
}

// ---------------------------------------------------------------------------
// Flash attention (causal), fp32 (unchanged; y output tf32-rounded for proj).
// ---------------------------------------------------------------------------
#define SQT_ST 68
#define SV_ST 132
#define ATT_SM_FLOATS (128 * SQT_ST + 128 * SQT_ST + 64 * SV_ST + 64 * 64)
#define ATT_SM_BYTES (ATT_SM_FLOATS * 4)

__global__ __launch_bounds__(256, 1) void attn_kernel(
    const float* __restrict__ Q, const float* __restrict__ K,
    const float* __restrict__ V, float* __restrict__ Y)
{
    extern __shared__ __align__(16) float smf[];
    float* sQT = smf;
    float* sKT = sQT + 128 * SQT_ST;
    float* sV  = sKT + 128 * SQT_ST;
    float* sP  = sV + 64 * SV_ST;

    const int qt = blockIdx.x;
    const int h  = blockIdx.y;
    const int b  = blockIdx.z;
    const int tid = threadIdx.x;
    const int ty = tid >> 4;
    const int tx = tid & 15;
    const int qbase = qt * 64;
    const size_t hb = ((size_t)(b * PH + h)) * PL * PHD;

    const int lrow = tid & 63;
    const int ldb  = (tid >> 6) * 32;

    {
        const float* qs = Q + hb + (size_t)(qbase + lrow) * PHD + ldb;
#pragma unroll
        for (int u = 0; u < 32; u += 4) {
            float4 f = *(const float4*)(qs + u);
            sQT[(ldb + u + 0) * SQT_ST + lrow] = f.x;
            sQT[(ldb + u + 1) * SQT_ST + lrow] = f.y;
            sQT[(ldb + u + 2) * SQT_ST + lrow] = f.z;
            sQT[(ldb + u + 3) * SQT_ST + lrow] = f.w;
        }
    }

    float m_i[4], l_i[4], o[4][8];
#pragma unroll
    for (int i = 0; i < 4; ++i) {
        m_i[i] = -1e30f;
        l_i[i] = 0.f;
#pragma unroll
        for (int j = 0; j < 8; ++j) o[i][j] = 0.f;
    }
    __syncthreads();

    const float scale = 0.08838834764831845f;

    for (int kt = 0; kt <= qt; ++kt) {
        const int kbase = kt * 64;
        {
            const float* ks = K + hb + (size_t)(kbase + lrow) * PHD + ldb;
#pragma unroll
            for (int u = 0; u < 32; u += 4) {
                float4 f = *(const float4*)(ks + u);
                sKT[(ldb + u + 0) * SQT_ST + lrow] = f.x;
                sKT[(ldb + u + 1) * SQT_ST + lrow] = f.y;
                sKT[(ldb + u + 2) * SQT_ST + lrow] = f.z;
                sKT[(ldb + u + 3) * SQT_ST + lrow] = f.w;
            }
            const float* vs = V + hb + (size_t)(kbase + lrow) * PHD + ldb;
            float* vd = sV + lrow * SV_ST + ldb;
#pragma unroll
            for (int u = 0; u < 32; u += 4)
                *(float4*)(vd + u) = *(const float4*)(vs + u);
        }
        __syncthreads();

        float s[4][4];
#pragma unroll
        for (int i = 0; i < 4; ++i)
#pragma unroll
            for (int j = 0; j < 4; ++j) s[i][j] = 0.f;

#pragma unroll 4
        for (int d = 0; d < 128; ++d) {
            float4 qv = *(const float4*)(sQT + d * SQT_ST + ty * 4);
            float4 kv = *(const float4*)(sKT + d * SQT_ST + tx * 4);
            float qa[4] = {qv.x, qv.y, qv.z, qv.w};
            float ka[4] = {kv.x, kv.y, kv.z, kv.w};
#pragma unroll
            for (int i = 0; i < 4; ++i)
#pragma unroll
                for (int j = 0; j < 4; ++j)
                    s[i][j] += qa[i] * ka[j];
        }

        if (kt == qt) {
#pragma unroll
            for (int i = 0; i < 4; ++i)
#pragma unroll
                for (int j = 0; j < 4; ++j)
                    s[i][j] = (tx * 4 + j > ty * 4 + i) ? -1e30f : s[i][j] * scale;
        } else {
#pragma unroll
            for (int i = 0; i < 4; ++i)
#pragma unroll
                for (int j = 0; j < 4; ++j)
                    s[i][j] *= scale;
        }

        float alpha[4];
#pragma unroll
        for (int i = 0; i < 4; ++i) {
            float rm = fmaxf(fmaxf(s[i][0], s[i][1]), fmaxf(s[i][2], s[i][3]));
#pragma unroll
            for (int off = 8; off > 0; off >>= 1)
                rm = fmaxf(rm, __shfl_xor_sync(0xffffffffu, rm, off));
            float mnew = fmaxf(m_i[i], rm);
            alpha[i] = __expf(m_i[i] - mnew);
            float rs = 0.f;
#pragma unroll
            for (int j = 0; j < 4; ++j) {
                s[i][j] = __expf(s[i][j] - mnew);
                rs += s[i][j];
            }
#pragma unroll
            for (int off = 8; off > 0; off >>= 1)
                rs += __shfl_xor_sync(0xffffffffu, rs, off);
            l_i[i] = l_i[i] * alpha[i] + rs;
            m_i[i] = mnew;
        }

#pragma unroll
        for (int i = 0; i < 4; ++i) {
#pragma unroll
            for (int j = 0; j < 8; ++j) o[i][j] *= alpha[i];
            float4 p4 = make_float4(s[i][0], s[i][1], s[i][2], s[i][3]);
            *(float4*)&sP[(ty * 4 + i) * 64 + tx * 4] = p4;
        }
        __syncthreads();

#pragma unroll 4
        for (int kk = 0; kk < 64; ++kk) {
            float4 va = *(const float4*)(sV + kk * SV_ST + tx * 4);
            float4 vb = *(const float4*)(sV + kk * SV_ST + 64 + tx * 4);
#pragma unroll
            for (int i = 0; i < 4; ++i) {
                float p = sP[(ty * 4 + i) * 64 + kk];
                o[i][0] += p * va.x; o[i][1] += p * va.y;
                o[i][2] += p * va.z; o[i][3] += p * va.w;
                o[i][4] += p * vb.x; o[i][5] += p * vb.y;
                o[i][6] += p * vb.z; o[i][7] += p * vb.w;
            }
        }
        __syncthreads();
    }

    // epilogue: normalize + tf32-round (y feeds the tf32 proj GEMM) + write
#pragma unroll
    for (int i = 0; i < 4; ++i) {
        float inv = 1.f / l_i[i];
        size_t r = ((size_t)(b * PL + qbase + ty * 4 + i)) * PE + h * PHD;
        float4 y0 = make_float4(to_tf32(o[i][0] * inv), to_tf32(o[i][1] * inv),
                                to_tf32(o[i][2] * inv), to_tf32(o[i][3] * inv));
        float4 y1 = make_float4(to_tf32(o[i][4] * inv), to_tf32(o[i][5] * inv),
                                to_tf32(o[i][6] * inv), to_tf32(o[i][7] * inv));
        *(float4*)&Y[r + tx * 4]      = y0;
        *(float4*)&Y[r + 64 + tx * 4] = y1;
    }
}

// ---------------------------------------------------------------------------
// launch
// ---------------------------------------------------------------------------
extern "C" void kernel_launch(void* const* d_in, const int* in_sizes, int n_in,
                              void* d_out, int out_size)
{
    (void)in_sizes; (void)n_in; (void)out_size;
    const float* x      = (const float*)d_in[0];
    const float* rope   = (const float*)d_in[1];
    const float* w_attn = (const float*)d_in[2];
    const float* w_proj = (const float*)d_in[3];
    float* out = (float*)d_out;

    float *qkv, *q, *k, *v, *y, *xr, *war, *wpr;
    cudaGetSymbolAddress((void**)&qkv, g_qkv);
    cudaGetSymbolAddress((void**)&q, g_q);
    cudaGetSymbolAddress((void**)&k, g_k);
    cudaGetSymbolAddress((void**)&v, g_v);
    cudaGetSymbolAddress((void**)&y, g_y);
    cudaGetSymbolAddress((void**)&xr, g_xr);
    cudaGetSymbolAddress((void**)&war, g_war);
    cudaGetSymbolAddress((void**)&wpr, g_wpr);

    cudaFuncSetAttribute(gemm_mma, cudaFuncAttributeMaxDynamicSharedMemorySize, GEMM_SMEM);
    cudaFuncSetAttribute(attn_kernel, cudaFuncAttributeMaxDynamicSharedMemorySize, ATT_SM_BYTES);

    // 0) pre-round GEMM inputs to tf32 (unbiased rna; HW tf32 use is then exact)
    {
        int n4x = (PB * PL * PE) / 4;
        int n4a = (3 * PE * PE) / 4;
        int n4p = (PE * PE) / 4;
        round_tf32_kernel<<<n4x / 256, 256>>>((const float4*)x, (float4*)xr, n4x);
        round_tf32_kernel<<<n4a / 256, 256>>>((const float4*)w_attn, (float4*)war, n4a);
        round_tf32_kernel<<<n4p / 256, 256>>>((const float4*)w_proj, (float4*)wpr, n4p);
    }

    // 1) QKV projection: [4096,2048] x [6144,2048]^T -> [4096,6144]  (tf32 HMMA)
    gemm_mma<<<dim3(3 * PE / BN, PB * PL / BM), 256, GEMM_SMEM>>>(
        xr, war, qkv, PB * PL, 3 * PE, PE);

    // 2) RoPE + split/permute
    rope_split_kernel<<<(PB * PL * PH * 64) / 256, 256>>>(qkv, rope, q, k, v);

    // 3) causal flash attention (fp32)
    attn_kernel<<<dim3(PL / 64, PH, PB), 256, ATT_SM_BYTES>>>(q, k, v, y);

    // 4) output projection: [4096,2048] x [2048,2048]^T -> [4096,2048]  (tf32 HMMA)
    gemm_mma<<<dim3(PE / BN, PB * PL / BM), 256, GEMM_SMEM>>>(
        y, wpr, out, PB * PL, PE, PE);
}

// round 7
// speedup vs baseline: 3.5517x; 1.9020x over previous
#include <cuda_runtime.h>
#include <math.h>
#include <cstdint>

// Problem constants
#define PB 2
#define PL 2048
#define PE 2048
#define PH 16
#define PHD 128

// Scratch (device globals: no allocation allowed in kernel_launch)
__device__ float g_qkv[PB * PL * 3 * PE];        // [B, L, 3E]
__device__ float g_q[PB * PH * PL * PHD];        // [B, H, L, HD] (tf32-rounded)
__device__ float g_k[PB * PH * PL * PHD];
__device__ float g_v[PB * PH * PL * PHD];
__device__ float g_y[PB * PL * PE];              // [B, L, E] (attention out, tf32-rounded)
__device__ float g_xr[PB * PL * PE];             // tf32-rounded x
__device__ float g_war[3 * PE * PE];             // tf32-rounded w_attn
__device__ float g_wpr[PE * PE];                 // tf32-rounded w_proj

// ---------------------------------------------------------------------------
// Helpers
// ---------------------------------------------------------------------------
__device__ __forceinline__ uint32_t smem_u32(const void* p) {
    uint32_t a;
    asm("{ .reg .u64 t; cvta.to.shared.u64 t, %1; cvt.u32.u64 %0, t; }" : "=r"(a) : "l"(p));
    return a;
}

__device__ __forceinline__ float to_tf32(float x) {
    uint32_t u;
    asm("cvt.rna.tf32.f32 %0, %1;" : "=r"(u) : "f"(x));
    return __uint_as_float(u);
}

__device__ __forceinline__ void cp_async16(uint32_t dst, const void* src) {
    asm volatile("cp.async.cg.shared.global [%0], [%1], 16;" :: "r"(dst), "l"(src));
}
__device__ __forceinline__ void cp_commit() {
    asm volatile("cp.async.commit_group;" ::: "memory");
}
template <int N>
__device__ __forceinline__ void cp_wait() {
    asm volatile("cp.async.wait_group %0;" :: "n"(N) : "memory");
}

__device__ __forceinline__ void mma_tf32_16n8k8(
    float& c0, float& c1, float& c2, float& c3,
    uint32_t a0, uint32_t a1, uint32_t a2, uint32_t a3,
    uint32_t b0, uint32_t b1)
{
    asm volatile(
        "mma.sync.aligned.m16n8k8.row.col.f32.tf32.tf32.f32 "
        "{%0,%1,%2,%3}, {%4,%5,%6,%7}, {%8,%9}, {%0,%1,%2,%3};"
        : "+f"(c0), "+f"(c1), "+f"(c2), "+f"(c3)
        : "r"(a0), "r"(a1), "r"(a2), "r"(a3), "r"(b0), "r"(b1));
}

// ---------------------------------------------------------------------------
// tf32 rounding pass
// ---------------------------------------------------------------------------
__global__ __launch_bounds__(256) void round_tf32_kernel(
    const float4* __restrict__ in, float4* __restrict__ out, int n4)
{
    int i = blockIdx.x * blockDim.x + threadIdx.x;
    if (i < n4) {
        float4 v = in[i];
        v.x = to_tf32(v.x); v.y = to_tf32(v.y);
        v.z = to_tf32(v.z); v.w = to_tf32(v.w);
        out[i] = v;
    }
}

// ---------------------------------------------------------------------------
// tf32 HMMA GEMM (NT): C[M,N] = A[M,K] * B[N,K]^T (unchanged from R5, passing)
// ---------------------------------------------------------------------------
#define BM 128
#define BN 128
#define BK 32
#define BKP 36
#define TILE_FLOATS (128 * BKP)
#define GEMM_SMEM (4 * TILE_FLOATS * 4)

__global__ __launch_bounds__(256, 2) void gemm_mma(
    const float* __restrict__ A, const float* __restrict__ B, float* __restrict__ C,
    int M, int N, int K)
{
    extern __shared__ __align__(16) float smg[];
    float* sA = smg;
    float* sB = smg + 2 * TILE_FLOATS;
    const uint32_t sAu = smem_u32(sA);
    const uint32_t sBu = smem_u32(sB);

    const int tid = threadIdx.x;
    const int wid = tid >> 5;
    const int lane = tid & 31;
    const int bm = blockIdx.y * BM;
    const int bn = blockIdx.x * BN;
    const int wm = wid >> 2;
    const int wn = wid & 3;
    const int g = lane >> 2;
    const int tg = lane & 3;
    const int nt = K >> 5;

    const float* agp[4];
    const float* bgp[4];
    uint32_t asp[4], bsp[4];
#pragma unroll
    for (int j = 0; j < 4; ++j) {
        int c = tid + 256 * j;
        int row = c >> 3, k4 = c & 7;
        agp[j] = A + (size_t)(bm + row) * K + k4 * 4;
        bgp[j] = B + (size_t)(bn + row) * K + k4 * 4;
        asp[j] = (uint32_t)(row * BKP + k4 * 4) * 4;
        bsp[j] = (uint32_t)(row * BKP + k4 * 4) * 4;
    }

    float acc[4][4][4];
#pragma unroll
    for (int i = 0; i < 4; ++i)
#pragma unroll
        for (int j = 0; j < 4; ++j)
#pragma unroll
            for (int q = 0; q < 4; ++q) acc[i][j][q] = 0.f;

#pragma unroll
    for (int j = 0; j < 4; ++j) {
        cp_async16(sAu + asp[j], agp[j]);
        cp_async16(sBu + bsp[j], bgp[j]);
    }
    cp_commit();

    const float* aw0 = sA + (wm * 64 + g) * BKP + tg;
    const float* bw0 = sB + (wn * 32 + g) * BKP + tg;

    for (int t = 0; t < nt; ++t) {
        if (t + 1 < nt) {
            const int nb = (t + 1) & 1;
            const uint32_t so = nb * TILE_FLOATS * 4;
            const size_t go = (size_t)(t + 1) * BK;
#pragma unroll
            for (int j = 0; j < 4; ++j) {
                cp_async16(sAu + so + asp[j], agp[j] + go);
                cp_async16(sBu + so + bsp[j], bgp[j] + go);
            }
            cp_commit();
            cp_wait<1>();
        } else {
            cp_wait<0>();
        }
        __syncthreads();

        const float* At = aw0 + (t & 1) * TILE_FLOATS;
        const float* Bt = bw0 + (t & 1) * TILE_FLOATS;

#pragma unroll
        for (int ks = 0; ks < 4; ++ks) {
            const int k0 = ks * 8;
            uint32_t af[4][4], bf[4][2];
#pragma unroll
            for (int mt = 0; mt < 4; ++mt) {
                const float* ap = At + mt * 16 * BKP + k0;
                af[mt][0] = __float_as_uint(ap[0]);
                af[mt][1] = __float_as_uint(ap[8 * BKP]);
                af[mt][2] = __float_as_uint(ap[4]);
                af[mt][3] = __float_as_uint(ap[8 * BKP + 4]);
            }
#pragma unroll
            for (int nti = 0; nti < 4; ++nti) {
                const float* bp = Bt + nti * 8 * BKP + k0;
                bf[nti][0] = __float_as_uint(bp[0]);
                bf[nti][1] = __float_as_uint(bp[4]);
            }
#pragma unroll
            for (int mt = 0; mt < 4; ++mt)
#pragma unroll
                for (int nti = 0; nti < 4; ++nti)
                    mma_tf32_16n8k8(acc[mt][nti][0], acc[mt][nti][1],
                                    acc[mt][nti][2], acc[mt][nti][3],
                                    af[mt][0], af[mt][1], af[mt][2], af[mt][3],
                                    bf[nti][0], bf[nti][1]);
        }
        __syncthreads();
    }

#pragma unroll
    for (int mt = 0; mt < 4; ++mt) {
        const int row0 = bm + wm * 64 + mt * 16 + g;
#pragma unroll
        for (int nti = 0; nti < 4; ++nti) {
            const int col = bn + wn * 32 + nti * 8 + 2 * tg;
            *(float2*)&C[(size_t)row0 * N + col] =
                make_float2(acc[mt][nti][0], acc[mt][nti][1]);
            *(float2*)&C[(size_t)(row0 + 8) * N + col] =
                make_float2(acc[mt][nti][2], acc[mt][nti][3]);
        }
    }
}

// ---------------------------------------------------------------------------
// RoPE + QKV split/permute; outputs rna-rounded to tf32 (feed HMMA attention)
// ---------------------------------------------------------------------------
__global__ __launch_bounds__(256) void rope_split_kernel(
    const float* __restrict__ qkv, const float* __restrict__ rope,
    float* __restrict__ q, float* __restrict__ k, float* __restrict__ v)
{
    int idx = blockIdx.x * blockDim.x + threadIdx.x;
    int i = idx & 63;
    int h = (idx >> 6) & (PH - 1);
    int l = (idx >> 10) & (PL - 1);
    int b = idx >> 21;

    float sn = rope[(l * 64 + i) * 2 + 0];
    float cs = rope[(l * 64 + i) * 2 + 1];

    size_t base = ((size_t)(b * PL + l)) * (3 * PE) + h * PHD + 2 * i;
    float q0 = qkv[base];
    float q1 = qkv[base + 1];
    float k0 = qkv[base + PE];
    float k1 = qkv[base + PE + 1];
    float v0 = qkv[base + 2 * PE];
    float v1 = qkv[base + 2 * PE + 1];

    size_t o = ((size_t)((b * PH + h) * PL + l)) * PHD + 2 * i;
    q[o]     = to_tf32(q0 * cs - q1 * sn);
    q[o + 1] = to_tf32(q1 * cs + q0 * sn);
    k[o]     = to_tf32(k0 * cs - k1 * sn);
    k[o + 1] = to_tf32(k1 * cs + k0 * sn);
    v[o]     = to_tf32(v0);
    v[o + 1] = to_tf32(v1);
}

// ---------------------------------------------------------------------------
// Flash attention (causal) with tf32 HMMA.
// CTA: 128 q-rows, 256 threads (8 warps, 16 rows/warp). k-tiles of 64.
// smem: sQ[128][132], sK[2][64][132], sV[64][136], sP[128][68].
// Loader chunk maps (FIXED in R7): rows are 128 floats = 32 float4 chunks.
//   Q: 4096 chunks -> 16/thread; K,V: 2048 chunks -> 8/thread.
// ---------------------------------------------------------------------------
#define AQ_ST 132
#define AK_ST 132
#define AV_ST 136
#define AP_ST 68
#define SQ_F  (128 * AQ_ST)
#define SK_F  (64 * AK_ST)
#define SV_F  (64 * AV_ST)
#define SP_F  (128 * AP_ST)
#define OFF_Q  0
#define OFF_K0 (SQ_F)
#define OFF_K1 (SQ_F + SK_F)
#define OFF_V  (SQ_F + 2 * SK_F)
#define OFF_P  (SQ_F + 2 * SK_F + SV_F)
#define ATT_SMEM ((OFF_P + SP_F) * 4)  // 204800 bytes

__global__ __launch_bounds__(256, 1) void attn_mma_kernel(
    const float* __restrict__ Q, const float* __restrict__ K,
    const float* __restrict__ V, float* __restrict__ Y)
{
    extern __shared__ __align__(16) float smf[];
    const uint32_t sb = smem_u32(smf);
    float* sQ = smf + OFF_Q;
    float* sV = smf + OFF_V;
    float* sP = smf + OFF_P;

    const int qt = gridDim.x - 1 - blockIdx.x;   // heavy CTAs first
    const int h  = blockIdx.y;
    const int b  = blockIdx.z;
    const int tid = threadIdx.x;
    const int wid = tid >> 5;
    const int lane = tid & 31;
    const int g = lane >> 2;
    const int tg = lane & 3;
    const int qbase = qt * 128;
    const size_t hb = ((size_t)(b * PH + h)) * PL * PHD;
    const int nkt = 2 * qt + 2;

    const float* Kbase = K + hb;
    const float* Vbase = V + hb;

    // ---- prologue loads ----
    // Q: 128 rows x 32 chunks = 4096 chunks, 16 per thread
    {
        const float* qsrc = Q + hb + (size_t)qbase * PHD;
#pragma unroll
        for (int j = 0; j < 16; ++j) {
            int c = tid + 256 * j;
            int row = c >> 5, k4 = (c & 31) * 4;
            cp_async16(sb + (uint32_t)(OFF_Q + row * AQ_ST + k4) * 4,
                       qsrc + (size_t)row * PHD + k4);
        }
        // K0: 64 rows x 32 chunks = 2048 chunks, 8 per thread
#pragma unroll
        for (int j = 0; j < 8; ++j) {
            int c = tid + 256 * j;
            int row = c >> 5, k4 = (c & 31) * 4;
            cp_async16(sb + (uint32_t)(OFF_K0 + row * AK_ST + k4) * 4,
                       Kbase + (size_t)row * PHD + k4);
        }
        cp_commit();   // group: {Q, K0}
#pragma unroll
        for (int j = 0; j < 8; ++j) {
            int c = tid + 256 * j;
            int row = c >> 5, k4 = (c & 31) * 4;
            cp_async16(sb + (uint32_t)(OFF_V + row * AV_ST + k4) * 4,
                       Vbase + (size_t)row * PHD + k4);
        }
        cp_commit();   // group: {V0}
    }

    const float scale = 0.08838834764831845f;   // 1/sqrt(128)

    float oacc[16][4];
#pragma unroll
    for (int i = 0; i < 16; ++i)
#pragma unroll
        for (int j = 0; j < 4; ++j) oacc[i][j] = 0.f;
    float m0 = -1e30f, m1 = -1e30f, l0 = 0.f, l1 = 0.f;

    const int wrow = wid * 16;                   // warp's q-row base (local)
    const float* aQ = sQ + (wrow + g) * AQ_ST + tg;
    const float* aP = sP + (wrow + g) * AP_ST + tg;

    for (int kt = 0; kt < nkt; ++kt) {
        const int kbase = kt * 64;
        const int buf = kt & 1;
        const float* sKt = smf + (buf ? OFF_K1 : OFF_K0);
        const float* bK = sKt + g * AK_ST + tg;

        cp_wait<1>();            // K_kt (and Q) ready
        __syncthreads();

        // ---- S = Q K^T : 16 k-chunks x 8 n-tiles ----
        float sacc[8][4];
#pragma unroll
        for (int n = 0; n < 8; ++n)
#pragma unroll
            for (int j = 0; j < 4; ++j) sacc[n][j] = 0.f;

#pragma unroll 4
        for (int kc = 0; kc < 16; ++kc) {
            const float* ap = aQ + kc * 8;
            uint32_t a0 = __float_as_uint(ap[0]);
            uint32_t a1 = __float_as_uint(ap[8 * AQ_ST]);
            uint32_t a2 = __float_as_uint(ap[4]);
            uint32_t a3 = __float_as_uint(ap[8 * AQ_ST + 4]);
#pragma unroll
            for (int n = 0; n < 8; ++n) {
                const float* bp = bK + n * 8 * AK_ST + kc * 8;
                mma_tf32_16n8k8(sacc[n][0], sacc[n][1], sacc[n][2], sacc[n][3],
                                a0, a1, a2, a3,
                                __float_as_uint(bp[0]), __float_as_uint(bp[4]));
            }
        }

        // prefetch next K into other buffer (overlaps softmax + PV)
        if (kt + 1 < nkt) {
            const uint32_t ko = (kt & 1) ? OFF_K0 : OFF_K1;
            const float* ksrc = Kbase + (size_t)(kbase + 64) * PHD;
#pragma unroll
            for (int j = 0; j < 8; ++j) {
                int c = tid + 256 * j;
                int row = c >> 5, k4 = (c & 31) * 4;
                cp_async16(sb + (uint32_t)(ko + row * AK_ST + k4) * 4,
                           ksrc + (size_t)row * PHD + k4);
            }
        }
        cp_commit();

        // ---- mask + scale + online softmax ----
        const int grow0 = qbase + wrow + g;
        const int grow1 = grow0 + 8;
        const bool diag = (kbase + 63 > qbase);
        float tm0 = -1e30f, tm1 = -1e30f;
#pragma unroll
        for (int n = 0; n < 8; ++n) {
            const int gc = kbase + n * 8 + 2 * tg;
            if (diag) {
                sacc[n][0] = (gc     > grow0) ? -1e30f : sacc[n][0] * scale;
                sacc[n][1] = (gc + 1 > grow0) ? -1e30f : sacc[n][1] * scale;
                sacc[n][2] = (gc     > grow1) ? -1e30f : sacc[n][2] * scale;
                sacc[n][3] = (gc + 1 > grow1) ? -1e30f : sacc[n][3] * scale;
            } else {
                sacc[n][0] *= scale; sacc[n][1] *= scale;
                sacc[n][2] *= scale; sacc[n][3] *= scale;
            }
            tm0 = fmaxf(tm0, fmaxf(sacc[n][0], sacc[n][1]));
            tm1 = fmaxf(tm1, fmaxf(sacc[n][2], sacc[n][3]));
        }
        tm0 = fmaxf(tm0, __shfl_xor_sync(0xffffffffu, tm0, 1));
        tm0 = fmaxf(tm0, __shfl_xor_sync(0xffffffffu, tm0, 2));
        tm1 = fmaxf(tm1, __shfl_xor_sync(0xffffffffu, tm1, 1));
        tm1 = fmaxf(tm1, __shfl_xor_sync(0xffffffffu, tm1, 2));

        const float mn0 = fmaxf(m0, tm0);
        const float mn1 = fmaxf(m1, tm1);
        const float al0 = __expf(m0 - mn0);
        const float al1 = __expf(m1 - mn1);
        m0 = mn0; m1 = mn1;

        float rs0 = 0.f, rs1 = 0.f;
#pragma unroll
        for (int n = 0; n < 8; ++n) {
            float p0 = to_tf32(__expf(sacc[n][0] - mn0));
            float p1 = to_tf32(__expf(sacc[n][1] - mn0));
            float p2 = to_tf32(__expf(sacc[n][2] - mn1));
            float p3 = to_tf32(__expf(sacc[n][3] - mn1));
            rs0 += p0 + p1; rs1 += p2 + p3;
            *(float2*)&sP[(wrow + g) * AP_ST + n * 8 + 2 * tg] = make_float2(p0, p1);
            *(float2*)&sP[(wrow + g + 8) * AP_ST + n * 8 + 2 * tg] = make_float2(p2, p3);
        }
        rs0 += __shfl_xor_sync(0xffffffffu, rs0, 1);
        rs0 += __shfl_xor_sync(0xffffffffu, rs0, 2);
        rs1 += __shfl_xor_sync(0xffffffffu, rs1, 1);
        rs1 += __shfl_xor_sync(0xffffffffu, rs1, 2);
        l0 = l0 * al0 + rs0;
        l1 = l1 * al1 + rs1;

#pragma unroll
        for (int n = 0; n < 16; ++n) {
            oacc[n][0] *= al0; oacc[n][1] *= al0;
            oacc[n][2] *= al1; oacc[n][3] *= al1;
        }

        cp_wait<1>();            // V_kt ready (next-K may still pend)
        __syncthreads();

        // ---- O += P V : 8 k-chunks x 16 n-tiles ----
#pragma unroll 2
        for (int c = 0; c < 8; ++c) {
            const float* ap = aP + c * 8;
            uint32_t a0 = __float_as_uint(ap[0]);
            uint32_t a1 = __float_as_uint(ap[8 * AP_ST]);
            uint32_t a2 = __float_as_uint(ap[4]);
            uint32_t a3 = __float_as_uint(ap[8 * AP_ST + 4]);
            const float* bv = sV + (c * 8 + tg) * AV_ST + g;
#pragma unroll
            for (int n = 0; n < 16; ++n) {
                const float* bp = bv + n * 8;
                mma_tf32_16n8k8(oacc[n][0], oacc[n][1], oacc[n][2], oacc[n][3],
                                a0, a1, a2, a3,
                                __float_as_uint(bp[0]),
                                __float_as_uint(bp[4 * AV_ST]));
            }
        }
        __syncthreads();          // everyone done reading sV (and sP)

        // prefetch next V (overlaps next S)
        if (kt + 1 < nkt) {
            const float* vsrc = Vbase + (size_t)(kbase + 64) * PHD;
#pragma unroll
            for (int j = 0; j < 8; ++j) {
                int c = tid + 256 * j;
                int row = c >> 5, k4 = (c & 31) * 4;
                cp_async16(sb + (uint32_t)(OFF_V + row * AV_ST + k4) * 4,
                           vsrc + (size_t)row * PHD + k4);
            }
        }
        cp_commit();
    }

    // ---- epilogue: normalize, tf32-round, write Y[b, l, h*128 + d] ----
    const float inv0 = 1.f / l0;
    const float inv1 = 1.f / l1;
    const int grow0 = qbase + wrow + g;
    float* y0 = Y + ((size_t)(b * PL + grow0)) * PE + h * PHD;
    float* y1 = Y + ((size_t)(b * PL + grow0 + 8)) * PE + h * PHD;
#pragma unroll
    for (int n = 0; n < 16; ++n) {
        const int col = n * 8 + 2 * tg;
        *(float2*)&y0[col] = make_float2(to_tf32(oacc[n][0] * inv0),
                                         to_tf32(oacc[n][1] * inv0));
        *(float2*)&y1[col] = make_float2(to_tf32(oacc[n][2] * inv1),
                                         to_tf32(oacc[n][3] * inv1));
    }
}

// ---------------------------------------------------------------------------
// launch
// ---------------------------------------------------------------------------
extern "C" void kernel_launch(void* const* d_in, const int* in_sizes, int n_in,
                              void* d_out, int out_size)
{
    (void)in_sizes; (void)n_in; (void)out_size;
    const float* x      = (const float*)d_in[0];
    const float* rope   = (const float*)d_in[1];
    const float* w_attn = (const float*)d_in[2];
    const float* w_proj = (const float*)d_in[3];
    float* out = (float*)d_out;

    float *qkv, *q, *k, *v, *y, *xr, *war, *wpr;
    cudaGetSymbolAddress((void**)&qkv, g_qkv);
    cudaGetSymbolAddress((void**)&q, g_q);
    cudaGetSymbolAddress((void**)&k, g_k);
    cudaGetSymbolAddress((void**)&v, g_v);
    cudaGetSymbolAddress((void**)&y, g_y);
    cudaGetSymbolAddress((void**)&xr, g_xr);
    cudaGetSymbolAddress((void**)&war, g_war);
    cudaGetSymbolAddress((void**)&wpr, g_wpr);

    cudaFuncSetAttribute(gemm_mma, cudaFuncAttributeMaxDynamicSharedMemorySize, GEMM_SMEM);
    cudaFuncSetAttribute(attn_mma_kernel, cudaFuncAttributeMaxDynamicSharedMemorySize, ATT_SMEM);

    // 0) pre-round GEMM inputs to tf32 (rna; HW tf32 use is then exact)
    {
        int n4x = (PB * PL * PE) / 4;
        int n4a = (3 * PE * PE) / 4;
        int n4p = (PE * PE) / 4;
        round_tf32_kernel<<<n4x / 256, 256>>>((const float4*)x, (float4*)xr, n4x);
        round_tf32_kernel<<<n4a / 256, 256>>>((const float4*)w_attn, (float4*)war, n4a);
        round_tf32_kernel<<<n4p / 256, 256>>>((const float4*)w_proj, (float4*)wpr, n4p);
    }

    // 1) QKV projection (tf32 HMMA)
    gemm_mma<<<dim3(3 * PE / BN, PB * PL / BM), 256, GEMM_SMEM>>>(
        xr, war, qkv, PB * PL, 3 * PE, PE);

    // 2) RoPE + split/permute (+ tf32 rounding of q,k,v)
    rope_split_kernel<<<(PB * PL * PH * 64) / 256, 256>>>(qkv, rope, q, k, v);

    // 3) causal flash attention (tf32 HMMA)
    attn_mma_kernel<<<dim3(PL / 128, PH, PB), 256, ATT_SMEM>>>(q, k, v, y);

    // 4) output projection (tf32 HMMA)
    gemm_mma<<<dim3(PE / BN, PB * PL / BM), 256, GEMM_SMEM>>>(
        y, wpr, out, PB * PL, PE, PE);
}